// round 12
// baseline (speedup 1.0000x reference)
#include <cuda_runtime.h>
#include <math.h>
#include <stdint.h>

#define T_TOKENS 16384
#define HID      2048
#define NEXP     64
#define BT       128
#define KT       32
#define NST      (HID / KT)        // 64
#define NBLOCKS  (T_TOKENS / BT)   // 128

#define OFF_MULT  0
#define OFF_GATES (T_TOKENS * 2)
#define OFF_SEL   (OFF_GATES + T_TOKENS * NEXP)
#define OFF_Z     (OFF_SEL + T_TOKENS * 2)

// smem layout (floats)
#define A_CST 132                  // A column stride (conflict-free LDS.64)
#define A_BUF (32 * A_CST)         // 4224 floats per A buffer
#define B_RST 40                   // B row stride (conflict-free LDS.64)
#define B_BUF (64 * B_RST)         // 2560 floats per B buffer
#define AH_O  0
#define AL_O  (2 * A_BUF)          // 8448
#define BH_O  (4 * A_BUF)          // 16896
#define BL_O  (BH_O + 2 * B_BUF)   // 22016
#define DYN_FLOATS (BL_O + 2 * B_BUF)   // 27136
#define DYN_BYTES  (DYN_FLOATS * 4)     // 108544
#define LS    68                   // logits stride (aliases dyn smem)

__device__ float g_zpart[NBLOCKS];

// storage column for logical k within a 32-k stage:
// cf and cf+4 of each k8 chunk stored adjacently (cols 2c, 2c+1)
__device__ __host__ __forceinline__ int CK(int kl) {
    return ((kl >> 3) << 3) + 2 * (kl & 3) + ((kl & 7) >> 2);
}

__device__ __forceinline__ float tf32_rna(float v) {
    uint32_t u; asm("cvt.rna.tf32.f32 %0, %1;" : "=r"(u) : "f"(v));
    return __uint_as_float(u);
}

__device__ __forceinline__ void mma_tf32(float* d,
                                         uint32_t a0, uint32_t a1, uint32_t a2, uint32_t a3,
                                         uint32_t b0, uint32_t b1) {
    asm volatile(
        "mma.sync.aligned.m16n8k8.row.col.f32.tf32.tf32.f32 "
        "{%0,%1,%2,%3}, {%4,%5,%6,%7}, {%8,%9}, {%0,%1,%2,%3};"
        : "+f"(d[0]), "+f"(d[1]), "+f"(d[2]), "+f"(d[3])
        : "r"(a0), "r"(a1), "r"(a2), "r"(a3), "r"(b0), "r"(b1));
}

extern __shared__ float sdyn[];

__global__ __launch_bounds__(256, 1)
void router_kernel(const float* __restrict__ x, const float* __restrict__ w,
                   float* __restrict__ out)
{
    __shared__ float Zs[BT];

    const int tid  = threadIdx.x;
    const int wid  = tid >> 5;
    const int lane = tid & 31;
    const int blk  = blockIdx.x;

    // ---------------- producer indexing ----------------
    const int tr = tid >> 1;                 // token row 0..127
    const int kh = (tid & 1) * 16;           // k half within stage
    const int posA = (tr >> 4) * 16 + 2 * (tr & 7) + ((tr & 15) >> 3);

    int aoff[16];
#pragma unroll
    for (int t = 0; t < 16; t++)
        aoff[t] = (kh + CK(t)) * A_CST + posA;

    const int bn = tid >> 2;                 // expert row 0..63
    const int kq = tid & 3;
    int boff[8];
#pragma unroll
    for (int t = 0; t < 8; t++) {
        int kl = kq * 4 + (t >> 2) * 16 + (t & 3);
        boff[t] = bn * B_RST + CK(kl);
    }

    const float4* xA = (const float4*)(x + (size_t)(blk * BT + tr) * HID + kh);
    const float4* wB = (const float4*)(w + (size_t)bn * HID + kq * 4);

    // ---------------- consumer indexing ----------------
    const int wm = (wid & 3) * 32;
    const int wn = (wid >> 2) * 32;
    const int fr = lane >> 2;                // 0..7
    const int fc = lane & 3;                 // 0..3

    // persistent fp32 accumulators (IEEE adds between stages)
    float acc[2][4][4];
#pragma unroll
    for (int mt = 0; mt < 2; mt++)
#pragma unroll
        for (int nt = 0; nt < 4; nt++)
#pragma unroll
            for (int q = 0; q < 4; q++) acc[mt][nt][q] = 0.f;

    // ---------------- prologue: fill stage 0 ----------------
    {
        float4 a4[4]; float4 b4[2];
#pragma unroll
        for (int j = 0; j < 4; j++) a4[j] = xA[j];
        b4[0] = wB[0]; b4[1] = wB[4];
        float* pAh = sdyn + AH_O; float* pAl = sdyn + AL_O;
        float* pBh = sdyn + BH_O; float* pBl = sdyn + BL_O;
        const float* av = (const float*)a4;
        const float* bv = (const float*)b4;
#pragma unroll
        for (int t = 0; t < 16; t++) {
            float v = av[t]; float h = tf32_rna(v); float l = tf32_rna(v - h);
            pAh[aoff[t]] = h; pAl[aoff[t]] = l;
        }
#pragma unroll
        for (int t = 0; t < 8; t++) {
            float v = bv[t]; float h = tf32_rna(v); float l = tf32_rna(v - h);
            pBh[boff[t]] = h; pBl[boff[t]] = l;
        }
    }
    __syncthreads();

    // ---------------- main pipeline ----------------
#pragma unroll 1
    for (int s = 0; s < NST; s++) {
        const int buf = s & 1;
        const bool pf = (s + 1 < NST);

        float4 a4[4]; float4 b4[2];
        if (pf) {
            const int f4 = (s + 1) * (KT / 4);
#pragma unroll
            for (int j = 0; j < 4; j++) a4[j] = xA[f4 + j];
            b4[0] = wB[f4]; b4[1] = wB[f4 + 4];
        }

        // MMA on current buffer -> per-stage temp accumulators
        {
            float tmp[2][4][4];
#pragma unroll
            for (int mt = 0; mt < 2; mt++)
#pragma unroll
                for (int nt = 0; nt < 4; nt++)
#pragma unroll
                    for (int q = 0; q < 4; q++) tmp[mt][nt][q] = 0.f;

            const float* pAh = sdyn + AH_O + buf * A_BUF;
            const float* pAl = sdyn + AL_O + buf * A_BUF;
            const float* pBh = sdyn + BH_O + buf * B_BUF;
            const float* pBl = sdyn + BL_O + buf * B_BUF;
#pragma unroll
            for (int kc = 0; kc < 4; kc++) {
                const int ca = (kc * 8 + 2 * fc) * A_CST + wm + 2 * fr;
                uint2 ah[2][2], al[2][2];
#pragma unroll
                for (int mt = 0; mt < 2; mt++) {
                    const int base = ca + mt * 16;
                    ah[mt][0] = *(const uint2*)&pAh[base];
                    ah[mt][1] = *(const uint2*)&pAh[base + A_CST];
                    al[mt][0] = *(const uint2*)&pAl[base];
                    al[mt][1] = *(const uint2*)&pAl[base + A_CST];
                }
                uint2 bh[4], bl[4];
#pragma unroll
                for (int nt = 0; nt < 4; nt++) {
                    const int bo = (wn + nt * 8 + fr) * B_RST + kc * 8 + 2 * fc;
                    bh[nt] = *(const uint2*)&pBh[bo];
                    bl[nt] = *(const uint2*)&pBl[bo];
                }
#pragma unroll
                for (int mt = 0; mt < 2; mt++)
#pragma unroll
                    for (int nt = 0; nt < 4; nt++)
                        mma_tf32(tmp[mt][nt],
                                 ah[mt][0].x, ah[mt][0].y, ah[mt][1].x, ah[mt][1].y,
                                 bh[nt].x, bh[nt].y);
#pragma unroll
                for (int mt = 0; mt < 2; mt++)
#pragma unroll
                    for (int nt = 0; nt < 4; nt++)
                        mma_tf32(tmp[mt][nt],
                                 ah[mt][0].x, ah[mt][0].y, ah[mt][1].x, ah[mt][1].y,
                                 bl[nt].x, bl[nt].y);
#pragma unroll
                for (int mt = 0; mt < 2; mt++)
#pragma unroll
                    for (int nt = 0; nt < 4; nt++)
                        mma_tf32(tmp[mt][nt],
                                 al[mt][0].x, al[mt][0].y, al[mt][1].x, al[mt][1].y,
                                 bh[nt].x, bh[nt].y);
            }

            // fold stage partial into persistent fp32 accumulators (IEEE adds)
#pragma unroll
            for (int mt = 0; mt < 2; mt++)
#pragma unroll
                for (int nt = 0; nt < 4; nt++)
#pragma unroll
                    for (int q = 0; q < 4; q++) acc[mt][nt][q] += tmp[mt][nt][q];
        }
        __syncthreads();   // all reads of current buffer complete

        if (pf) {
            const int nbuf = buf ^ 1;
            float* pAh = sdyn + AH_O + nbuf * A_BUF;
            float* pAl = sdyn + AL_O + nbuf * A_BUF;
            float* pBh = sdyn + BH_O + nbuf * B_BUF;
            float* pBl = sdyn + BL_O + nbuf * B_BUF;
            const float* av = (const float*)a4;
            const float* bv = (const float*)b4;
#pragma unroll
            for (int t = 0; t < 16; t++) {
                float v = av[t]; float h = tf32_rna(v); float l = tf32_rna(v - h);
                pAh[aoff[t]] = h; pAl[aoff[t]] = l;
            }
#pragma unroll
            for (int t = 0; t < 8; t++) {
                float v = bv[t]; float h = tf32_rna(v); float l = tf32_rna(v - h);
                pBh[boff[t]] = h; pBl[boff[t]] = l;
            }
            __syncthreads();
        }
    }

    // ---------------- C fragments -> logits smem ----------------
    float* lg = sdyn;   // [BT][LS], aliases stage buffers (safe: synced above)
#pragma unroll
    for (int mt = 0; mt < 2; mt++)
#pragma unroll
        for (int nt = 0; nt < 4; nt++) {
            const int t0 = wm + mt * 16 + fr;
            const int c  = wn + nt * 8 + fc * 2;
            float2 lo2, hi2;
            lo2.x = acc[mt][nt][0]; lo2.y = acc[mt][nt][1];
            hi2.x = acc[mt][nt][2]; hi2.y = acc[mt][nt][3];
            *(float2*)&lg[t0 * LS + c]       = lo2;
            *(float2*)&lg[(t0 + 8) * LS + c] = hi2;
        }
    __syncthreads();

    // ---------------- routing: thread t owns token t ----------------
    if (tid < BT) {
        const int tg = blk * BT + tid;
        const float NEG_INF = __int_as_float(0xff800000);

        float l[64];
#pragma unroll
        for (int c = 0; c < 64; c += 4) {
            float4 v = *(const float4*)&lg[tid * LS + c];
            l[c] = v.x; l[c + 1] = v.y; l[c + 2] = v.z; l[c + 3] = v.w;
        }

        // pass 1: max + first-index argmax
        float mx = l[0]; int ax = 0;
#pragma unroll
        for (int i = 1; i < 64; i++)
            if (l[i] > mx) { mx = l[i]; ax = i; }

        float so = 0.f, s1 = 0.f;
#pragma unroll
        for (int i = 0; i < 64; i++) {
            float e = expf(l[i] - mx);
            so += e;
            float f = fmaxf(fabsf(l[i]), mx);
            if (!((mx - l[i]) / f > 0.02f)) s1 += e;   // NaN-exact mask semantics
        }

        // pass 2: mask out ax
        float mx2 = NEG_INF; int ax2 = 0;
#pragma unroll
        for (int i = 0; i < 64; i++) {
            float v = (i == ax) ? NEG_INF : l[i];
            if (v > mx2) { mx2 = v; ax2 = i; }
        }
        float s2 = 0.f;
#pragma unroll
        for (int i = 0; i < 64; i++) {
            if (i != ax) {
                float f = fmaxf(fabsf(l[i]), mx2);
                if (!((mx2 - l[i]) / f > 0.02f)) s2 += expf(l[i] - mx2);
            }
        }

        const float inv = 1.f / so;
        float* gout = out + OFF_GATES + (size_t)tg * NEXP;
#pragma unroll
        for (int c = 0; c < 64; c += 4) {
            float4 g;
            g.x = expf(l[c + 0] - mx) * inv;
            g.y = expf(l[c + 1] - mx) * inv;
            g.z = expf(l[c + 2] - mx) * inv;
            g.w = expf(l[c + 3] - mx) * inv;
            *(float4*)(gout + c) = g;
        }
        out[OFF_MULT + tg * 2 + 0] = 1.f / s1;
        out[OFF_MULT + tg * 2 + 1] = 1.f / s2;
        out[OFF_SEL  + tg * 2 + 0] = (float)ax;
        out[OFF_SEL  + tg * 2 + 1] = (float)ax2;
        float lse = mx + logf(so);
        Zs[tid] = lse * lse;
    }
    __syncthreads();

    if (tid < 32) {
        float v = ((Zs[tid] + Zs[tid + 32]) + Zs[tid + 64]) + Zs[tid + 96];
#pragma unroll
        for (int mm = 16; mm; mm >>= 1) v += __shfl_xor_sync(0xffffffffu, v, mm, 32);
        if (tid == 0) g_zpart[blk] = v;
    }
}

__global__ void zfinal_kernel(float* __restrict__ out)
{
    __shared__ float s[NBLOCKS];
    const int t = threadIdx.x;
    s[t] = g_zpart[t];
    __syncthreads();
#pragma unroll
    for (int st = NBLOCKS / 2; st > 0; st >>= 1) {
        if (t < st) s[t] += s[t + st];
        __syncthreads();
    }
    if (t == 0) out[OFF_Z] = 0.001f * s[0] / (float)T_TOKENS;
}

extern "C" void kernel_launch(void* const* d_in, const int* in_sizes, int n_in,
                              void* d_out, int out_size)
{
    const float* x = (const float*)d_in[0];
    const float* w = (const float*)d_in[1];
    float* out = (float*)d_out;
    cudaFuncSetAttribute(router_kernel, cudaFuncAttributeMaxDynamicSharedMemorySize, DYN_BYTES);
    router_kernel<<<NBLOCKS, 256, DYN_BYTES>>>(x, w, out);
    zfinal_kernel<<<1, NBLOCKS>>>(out);
}